// round 6
// baseline (speedup 1.0000x reference)
#include <cuda_runtime.h>

#define N_ROWS   1000000
#define D        64
#define INNER    16
#define NTRI     136            // 16*17/2
#define NOUT     152            // NTRI + INNER  (= 38 float4)
#define NSEG     100000
#define OUTD     64
#define TPB      128
#define HALF_ROWS 500000

// Per-segment scratch: [0:16) = t accumulation, [16:152) = F lower-triangle accumulation
__device__ __align__(16) float g_scratch[(size_t)NSEG * NOUT];

__device__ __forceinline__ unsigned long long ffma2(unsigned long long a,
                                                    unsigned long long b,
                                                    unsigned long long c) {
    unsigned long long d;
    asm("fma.rn.f32x2 %0, %1, %2, %3;" : "=l"(d) : "l"(a), "l"(b), "l"(c));
    return d;
}

__device__ __forceinline__ void red_v4(float* p, float a, float b, float c, float d) {
    asm volatile("red.global.add.v4.f32 [%0], {%1, %2, %3, %4};"
                 :: "l"(p), "f"(a), "f"(b), "f"(c), "f"(d) : "memory");
}

__device__ __forceinline__ constexpr int TRI(int i, int j) { return i * (i + 1) / 2 + j; }

// fast tanh: 1 - 2/(exp(2x)+1).  2 MUFU + few ALU, ~1e-6 abs err.
__device__ __forceinline__ float fast_tanh(float x) {
    float e = __expf(2.0f * x);
    return 1.0f - __fdividef(2.0f, e + 1.0f);
}

// ---------------------------------------------------------------------------
// Kernel 0: zero the segment scratch
// ---------------------------------------------------------------------------
__global__ void zero_kernel() {
    size_t i = (size_t)blockIdx.x * blockDim.x + threadIdx.x;
    const size_t n4 = (size_t)NSEG * NOUT / 4;
    if (i < n4) {
        ((float4*)g_scratch)[i] = make_float4(0.f, 0.f, 0.f, 0.f);
    }
}

// ---------------------------------------------------------------------------
// Kernel 1: one thread per row. GEMM 64x152 (packed f32x2, MLP=4 front-batched
// streaming loads), t reds, in-place tanh->L, F=LL^T fired 4-at-a-time.
// Launched twice (disjoint [row_base, row_end) ranges) so ncu's capture slot
// lands on it.
// ---------------------------------------------------------------------------
__global__ __launch_bounds__(TPB) void main_kernel(const float4* __restrict__ data4,
                                                   const int* __restrict__ segs,
                                                   const float* __restrict__ W,
                                                   const float* __restrict__ b,
                                                   int row_base, int row_end) {
    __shared__ __align__(16) float W_s[D * NOUT];
    __shared__ __align__(16) float b_s[NOUT];

    for (int i = threadIdx.x; i < D * NOUT; i += TPB) W_s[i] = W[i];
    for (int i = threadIdx.x; i < NOUT; i += TPB) b_s[i] = b[i];
    __syncthreads();

    int row = row_base + blockIdx.x * TPB + threadIdx.x;
    if (row >= row_end) return;

    // ---- accumulators: 76 packed f32x2 pairs, init from bias ----
    unsigned long long acc2[NOUT / 2];
    const unsigned long long* b2 = (const unsigned long long*)b_s;
#pragma unroll
    for (int j = 0; j < NOUT / 2; j++) acc2[j] = b2[j];

    // ---- GEMM: net = x @ W + b  (k-loop unrolled 4, loads front-batched) ----
    const float4* dptr = data4 + (size_t)row * (D / 4);
#pragma unroll 1
    for (int kk = 0; kk < D / 4; kk += 4) {
        float4 xv[4];
#pragma unroll
        for (int u = 0; u < 4; u++) xv[u] = __ldcs(dptr + kk + u);   // 4x LDG.128, MLP=4
#pragma unroll
        for (int u = 0; u < 4; u++) {
            float xs[4] = {xv[u].x, xv[u].y, xv[u].z, xv[u].w};
#pragma unroll
            for (int ks = 0; ks < 4; ks++) {
                unsigned long long xx;
                asm("mov.b64 %0, {%1, %1};" : "=l"(xx) : "r"(__float_as_uint(xs[ks])));
                const ulonglong2* Wrow =
                    (const ulonglong2*)(W_s + ((kk + u) * 4 + ks) * NOUT);
#pragma unroll
                for (int jp = 0; jp < NOUT / 4; jp++) {   // 38 LDS.128 (broadcast), 76 FFMA2
                    ulonglong2 w = Wrow[jp];
                    acc2[2 * jp]     = ffma2(w.x, xx, acc2[2 * jp]);
                    acc2[2 * jp + 1] = ffma2(w.y, xx, acc2[2 * jp + 1]);
                }
            }
        }
    }

    // ---- unpack (register rename, not a copy) ----
    float net[NOUT];
#pragma unroll
    for (int j = 0; j < NOUT / 2; j++) {
        unsigned int lo, hi;
        asm("mov.b64 {%0, %1}, %2;" : "=r"(lo), "=r"(hi) : "l"(acc2[j]));
        net[2 * j]     = __uint_as_float(lo);
        net[2 * j + 1] = __uint_as_float(hi);
    }

    int seg = __ldg(segs + row);
    float* base = g_scratch + (size_t)seg * NOUT;

    // ---- t reductions (first 16 outputs): 4 x red.v4 ----
#pragma unroll
    for (int q = 0; q < INNER; q += 4)
        red_v4(base + q, net[q], net[q + 1], net[q + 2], net[q + 3]);

    // ---- L in place over net[16..152): tanh, diag -> softplus(tanh) ----
#pragma unroll
    for (int i = 0; i < INNER; i++) {
#pragma unroll
        for (int k = 0; k <= i; k++) {
            int m = TRI(i, k);
            float v = fast_tanh(net[INNER + m]);
            if (k == i) v = __logf(1.0f + __expf(v));   // softplus, arg in (-1,1): safe
            net[INNER + m] = v;
        }
    }

    // ---- F = L L^T lower triangle, fired 4-at-a-time (m order == TRI order) ----
    float fbuf[4];
#pragma unroll
    for (int i = 0; i < INNER; i++) {
#pragma unroll
        for (int j = 0; j <= i; j++) {
            float acc = 0.f;
#pragma unroll
            for (int k = 0; k <= j; k++)
                acc = fmaf(net[INNER + TRI(i, k)], net[INNER + TRI(j, k)], acc);
            int m = TRI(i, j);
            fbuf[m & 3] = acc;
            if ((m & 3) == 3)
                red_v4(base + INNER + (m & ~3), fbuf[0], fbuf[1], fbuf[2], fbuf[3]);
        }
    }
}

// ---------------------------------------------------------------------------
// Kernel 2: per-segment Cholesky solve + projection.
// theta[s,j] = ((F+I)^{-1} 1)_j * t_red[s,j]  (F+I symmetric)
// Then out[s,:] = theta @ proj_W.   One thread per segment.
// ---------------------------------------------------------------------------
__global__ __launch_bounds__(256) void solve_kernel(const float* __restrict__ proj,
                                                    float* __restrict__ out) {
    __shared__ float pw[INNER * OUTD];
    for (int i = threadIdx.x; i < INNER * OUTD; i += blockDim.x) pw[i] = proj[i];
    __syncthreads();

    int s = blockIdx.x * blockDim.x + threadIdx.x;
    if (s >= NSEG) return;

    const float4* base4 = (const float4*)(g_scratch + (size_t)s * NOUT);
    float buf[NOUT];
#pragma unroll
    for (int q = 0; q < NOUT / 4; q++) {
        float4 v = base4[q];
        buf[4 * q] = v.x; buf[4 * q + 1] = v.y; buf[4 * q + 2] = v.z; buf[4 * q + 3] = v.w;
    }

    float* A = buf + INNER;          // 136 packed lower-tri
#pragma unroll
    for (int i = 0; i < INNER; i++) A[TRI(i, i)] += 1.0f;   // F_masked = F_red + I

    // Cholesky (lower, packed). SPD guaranteed: sum of L L^T + I.
    for (int j = 0; j < INNER; j++) {
        float d = A[TRI(j, j)];
        for (int k = 0; k < j; k++) d -= A[TRI(j, k)] * A[TRI(j, k)];
        d = sqrtf(d);
        A[TRI(j, j)] = d;
        float inv = 1.0f / d;
        for (int i = j + 1; i < INNER; i++) {
            float v = A[TRI(i, j)];
            for (int k = 0; k < j; k++) v -= A[TRI(i, k)] * A[TRI(j, k)];
            A[TRI(i, j)] = v * inv;
        }
    }

    // Solve (F+I) c = 1  via  L z = 1, L^T c = z
    float z[INNER];
    for (int i = 0; i < INNER; i++) {
        float v = 1.0f;
        for (int k = 0; k < i; k++) v -= A[TRI(i, k)] * z[k];
        z[i] = v / A[TRI(i, i)];
    }
    float c[INNER];
    for (int i = INNER - 1; i >= 0; i--) {
        float v = z[i];
        for (int k = i + 1; k < INNER; k++) v -= A[TRI(k, i)] * c[k];
        c[i] = v / A[TRI(i, i)];
    }

    float th[INNER];
#pragma unroll
    for (int j = 0; j < INNER; j++) th[j] = c[j] * buf[j];

    float* orow = out + (size_t)s * OUTD;
#pragma unroll 4
    for (int o = 0; o < OUTD; o += 4) {
        float a0 = 0.f, a1 = 0.f, a2 = 0.f, a3 = 0.f;
#pragma unroll
        for (int j = 0; j < INNER; j++) {
            float t = th[j];
            a0 = fmaf(t, pw[j * OUTD + o],     a0);
            a1 = fmaf(t, pw[j * OUTD + o + 1], a1);
            a2 = fmaf(t, pw[j * OUTD + o + 2], a2);
            a3 = fmaf(t, pw[j * OUTD + o + 3], a3);
        }
        ((float4*)orow)[o / 4] = make_float4(a0, a1, a2, a3);
    }
}

// ---------------------------------------------------------------------------
extern "C" void kernel_launch(void* const* d_in, const int* in_sizes, int n_in,
                              void* d_out, int out_size) {
    const float* data = nullptr;
    const int*   segs = nullptr;
    const float* W    = nullptr;
    const float* b    = nullptr;
    const float* pw   = nullptr;

    for (int i = 0; i < n_in; i++) {
        switch (in_sizes[i]) {
            case N_ROWS * D:   data = (const float*)d_in[i]; break;   // 64,000,000
            case N_ROWS:       segs = (const int*)d_in[i];   break;   // 1,000,000
            case D * NOUT:     W    = (const float*)d_in[i]; break;   // 9,728
            case NOUT:         b    = (const float*)d_in[i]; break;   // 152
            case INNER * OUTD: pw   = (const float*)d_in[i]; break;   // 1,024
            default: break;                                            // num_segments scalar etc.
        }
    }

    const int n4 = NSEG * NOUT / 4;
    const int half_blocks = (HALF_ROWS + TPB - 1) / TPB;   // 3907
    zero_kernel<<<(n4 + 255) / 256, 256>>>();
    // Disjoint ranges: [0, 500000) and [500000, 1000000). Guard uses row_end.
    main_kernel<<<half_blocks, TPB>>>((const float4*)data, segs, W, b, 0, HALF_ROWS);
    main_kernel<<<half_blocks, TPB>>>((const float4*)data, segs, W, b, HALF_ROWS, N_ROWS);
    solve_kernel<<<(NSEG + 255) / 256, 256>>>(pw, (float*)d_out);
}

// round 7
// speedup vs baseline: 1.3283x; 1.3283x over previous
#include <cuda_runtime.h>

#define N_ROWS   1000000
#define D        64
#define INNER    16
#define NTRI     136            // 16*17/2
#define NOUT     152            // NTRI + INNER  (= 38 float4)
#define NSEG     100000
#define OUTD     64
#define TPB      128

// Per-segment scratch: [0:16) = t accumulation, [16:152) = F lower-triangle accumulation
__device__ __align__(16) float g_scratch[(size_t)NSEG * NOUT];

__device__ __forceinline__ unsigned long long ffma2(unsigned long long a,
                                                    unsigned long long b,
                                                    unsigned long long c) {
    unsigned long long d;
    asm("fma.rn.f32x2 %0, %1, %2, %3;" : "=l"(d) : "l"(a), "l"(b), "l"(c));
    return d;
}

__device__ __forceinline__ void red_v4(float* p, float a, float b, float c, float d) {
    asm volatile("red.global.add.v4.f32 [%0], {%1, %2, %3, %4};"
                 :: "l"(p), "f"(a), "f"(b), "f"(c), "f"(d) : "memory");
}

__device__ __forceinline__ constexpr int TRI(int i, int j) { return i * (i + 1) / 2 + j; }

// fast tanh: 1 - 2/(exp(2x)+1).  2 MUFU + few ALU, ~1e-6 abs err.
__device__ __forceinline__ float fast_tanh(float x) {
    float e = __expf(2.0f * x);
    return 1.0f - __fdividef(2.0f, e + 1.0f);
}

// ---------------------------------------------------------------------------
// Kernel 0: zero the segment scratch
// ---------------------------------------------------------------------------
__global__ void zero_kernel() {
    size_t i = (size_t)blockIdx.x * blockDim.x + threadIdx.x;
    const size_t n4 = (size_t)NSEG * NOUT / 4;
    if (i < n4) {
        ((float4*)g_scratch)[i] = make_float4(0.f, 0.f, 0.f, 0.f);
    }
}

// ---------------------------------------------------------------------------
// Kernel 1 (round-4 measured-best form): one thread per row.
// GEMM 64x152 (packed f32x2), t reds, in-place tanh->L, F=LL^T fired
// 4-at-a-time via red.global.add.v4.f32.
// ---------------------------------------------------------------------------
__global__ __launch_bounds__(TPB) void main_kernel(const float4* __restrict__ data4,
                                                   const int* __restrict__ segs,
                                                   const float* __restrict__ W,
                                                   const float* __restrict__ b) {
    __shared__ __align__(16) float W_s[D * NOUT];
    __shared__ __align__(16) float b_s[NOUT];

    for (int i = threadIdx.x; i < D * NOUT; i += TPB) W_s[i] = W[i];
    for (int i = threadIdx.x; i < NOUT; i += TPB) b_s[i] = b[i];
    __syncthreads();

    int row = blockIdx.x * TPB + threadIdx.x;
    if (row >= N_ROWS) return;

    // ---- accumulators: 76 packed f32x2 pairs, init from bias ----
    unsigned long long acc2[NOUT / 2];
    const unsigned long long* b2 = (const unsigned long long*)b_s;
#pragma unroll
    for (int j = 0; j < NOUT / 2; j++) acc2[j] = b2[j];

    // ---- GEMM: net = x @ W + b ----
    const float4* dptr = data4 + (size_t)row * (D / 4);
#pragma unroll 1
    for (int kk = 0; kk < D / 4; kk++) {
        float4 xv = dptr[kk];
        float xs[4] = {xv.x, xv.y, xv.z, xv.w};
#pragma unroll
        for (int ks = 0; ks < 4; ks++) {
            unsigned long long xx;
            asm("mov.b64 %0, {%1, %1};" : "=l"(xx) : "r"(__float_as_uint(xs[ks])));
            const ulonglong2* Wrow = (const ulonglong2*)(W_s + (kk * 4 + ks) * NOUT);
#pragma unroll
            for (int jp = 0; jp < NOUT / 4; jp++) {   // 38 x LDS.128 (broadcast), 76 x FFMA2
                ulonglong2 w = Wrow[jp];
                acc2[2 * jp]     = ffma2(w.x, xx, acc2[2 * jp]);
                acc2[2 * jp + 1] = ffma2(w.y, xx, acc2[2 * jp + 1]);
            }
        }
    }

    // ---- unpack (register rename, not a copy) ----
    float net[NOUT];
#pragma unroll
    for (int j = 0; j < NOUT / 2; j++) {
        unsigned int lo, hi;
        asm("mov.b64 {%0, %1}, %2;" : "=r"(lo), "=r"(hi) : "l"(acc2[j]));
        net[2 * j]     = __uint_as_float(lo);
        net[2 * j + 1] = __uint_as_float(hi);
    }

    int seg = segs[row];
    float* base = g_scratch + (size_t)seg * NOUT;

    // ---- t reductions (first 16 outputs): 4 x red.v4 ----
#pragma unroll
    for (int q = 0; q < INNER; q += 4)
        red_v4(base + q, net[q], net[q + 1], net[q + 2], net[q + 3]);

    // ---- L in place over net[16..152): tanh, diag -> softplus(tanh) ----
#pragma unroll
    for (int i = 0; i < INNER; i++) {
#pragma unroll
        for (int k = 0; k <= i; k++) {
            int m = TRI(i, k);
            float v = fast_tanh(net[INNER + m]);
            if (k == i) v = __logf(1.0f + __expf(v));   // softplus, arg in (-1,1): safe
            net[INNER + m] = v;
        }
    }

    // ---- F = L L^T lower triangle, fired 4-at-a-time (m order == TRI order) ----
    float fbuf[4];
#pragma unroll
    for (int i = 0; i < INNER; i++) {
#pragma unroll
        for (int j = 0; j <= i; j++) {
            float acc = 0.f;
#pragma unroll
            for (int k = 0; k <= j; k++)
                acc = fmaf(net[INNER + TRI(i, k)], net[INNER + TRI(j, k)], acc);
            int m = TRI(i, j);
            fbuf[m & 3] = acc;
            if ((m & 3) == 3)
                red_v4(base + INNER + (m & ~3), fbuf[0], fbuf[1], fbuf[2], fbuf[3]);
        }
    }
}

// ---------------------------------------------------------------------------
// Kernel 2: per-segment Cholesky solve + projection — FULLY UNROLLED so A/z/c
// live in registers (previous version: runtime loop indices forced buf[] into
// local memory -> 198us latency-bound kernel at 15% issue).
// theta[s,j] = ((F+I)^{-1} 1)_j * t_red[s,j]; out[s,:] = theta @ proj_W.
// One thread per segment.
// ---------------------------------------------------------------------------
__global__ __launch_bounds__(TPB) void solve_kernel(const float* __restrict__ proj,
                                                    float* __restrict__ out) {
    __shared__ float pw[INNER * OUTD];
    for (int i = threadIdx.x; i < INNER * OUTD; i += TPB) pw[i] = proj[i];
    __syncthreads();

    int s = blockIdx.x * TPB + threadIdx.x;
    if (s >= NSEG) return;

    const float* base = g_scratch + (size_t)s * NOUT;

    // ---- load F lower-triangle (136 floats = 34 float4) into registers ----
    float A[NTRI];
    const float4* f4 = (const float4*)(base + INNER);
#pragma unroll
    for (int q = 0; q < NTRI / 4; q++) {
        float4 v = f4[q];
        A[4 * q] = v.x; A[4 * q + 1] = v.y; A[4 * q + 2] = v.z; A[4 * q + 3] = v.w;
    }
#pragma unroll
    for (int i = 0; i < INNER; i++) A[TRI(i, i)] += 1.0f;   // F_masked = F_red + I

    // ---- Cholesky, fully unrolled (all indices compile-time) ----
#pragma unroll
    for (int j = 0; j < INNER; j++) {
        float d = A[TRI(j, j)];
#pragma unroll
        for (int k = 0; k < j; k++) d -= A[TRI(j, k)] * A[TRI(j, k)];
        d = sqrtf(d);
        A[TRI(j, j)] = d;
        float inv = __frcp_rn(d);
#pragma unroll
        for (int i = j + 1; i < INNER; i++) {
            float v = A[TRI(i, j)];
#pragma unroll
            for (int k = 0; k < j; k++) v -= A[TRI(i, k)] * A[TRI(j, k)];
            A[TRI(i, j)] = v * inv;
        }
    }

    // ---- Solve (F+I) c = 1 via L z = 1, L^T c = z (unrolled) ----
    float z[INNER];
#pragma unroll
    for (int i = 0; i < INNER; i++) {
        float v = 1.0f;
#pragma unroll
        for (int k = 0; k < i; k++) v -= A[TRI(i, k)] * z[k];
        z[i] = v * __frcp_rn(A[TRI(i, i)]);
    }
    float c[INNER];
#pragma unroll
    for (int i = INNER - 1; i >= 0; i--) {
        float v = z[i];
#pragma unroll
        for (int k = i + 1; k < INNER; k++) v -= A[TRI(k, i)] * c[k];
        c[i] = v * __frcp_rn(A[TRI(i, i)]);
    }

    // ---- theta = c * t_red (t loaded late to trim peak register pressure) ----
    float th[INNER];
    const float4* t4 = (const float4*)base;
#pragma unroll
    for (int q = 0; q < INNER / 4; q++) {
        float4 v = t4[q];
        th[4 * q]     = c[4 * q]     * v.x;
        th[4 * q + 1] = c[4 * q + 1] * v.y;
        th[4 * q + 2] = c[4 * q + 2] * v.z;
        th[4 * q + 3] = c[4 * q + 3] * v.w;
    }

    // ---- out = theta @ proj_W ----
    float* orow = out + (size_t)s * OUTD;
#pragma unroll 4
    for (int o = 0; o < OUTD; o += 4) {
        float a0 = 0.f, a1 = 0.f, a2 = 0.f, a3 = 0.f;
#pragma unroll
        for (int j = 0; j < INNER; j++) {
            float t = th[j];
            a0 = fmaf(t, pw[j * OUTD + o],     a0);
            a1 = fmaf(t, pw[j * OUTD + o + 1], a1);
            a2 = fmaf(t, pw[j * OUTD + o + 2], a2);
            a3 = fmaf(t, pw[j * OUTD + o + 3], a3);
        }
        ((float4*)orow)[o / 4] = make_float4(a0, a1, a2, a3);
    }
}

// ---------------------------------------------------------------------------
extern "C" void kernel_launch(void* const* d_in, const int* in_sizes, int n_in,
                              void* d_out, int out_size) {
    const float* data = nullptr;
    const int*   segs = nullptr;
    const float* W    = nullptr;
    const float* b    = nullptr;
    const float* pw   = nullptr;

    for (int i = 0; i < n_in; i++) {
        switch (in_sizes[i]) {
            case N_ROWS * D:   data = (const float*)d_in[i]; break;   // 64,000,000
            case N_ROWS:       segs = (const int*)d_in[i];   break;   // 1,000,000
            case D * NOUT:     W    = (const float*)d_in[i]; break;   // 9,728
            case NOUT:         b    = (const float*)d_in[i]; break;   // 152
            case INNER * OUTD: pw   = (const float*)d_in[i]; break;   // 1,024
            default: break;                                            // num_segments scalar etc.
        }
    }

    const int n4 = NSEG * NOUT / 4;
    zero_kernel<<<(n4 + 255) / 256, 256>>>();
    main_kernel<<<(N_ROWS + TPB - 1) / TPB, TPB>>>((const float4*)data, segs, W, b);
    solve_kernel<<<(NSEG + TPB - 1) / TPB, TPB>>>(pw, (float*)d_out);
}